// round 9
// baseline (speedup 1.0000x reference)
#include <cuda_runtime.h>
#include <cstdint>

// GRU decoder (Keras reset_after=True), B=32768, T=48, F=16, H=32, fp32.
// R8 structure (batch-packed f32x2, lane j = neuron j, 4 batches/warp as two
// pairs, h/features broadcast via per-warp shared buffers) with ALL weights
// moved to shared (per-lane-distinct 128B rows, 1 wavefront each) so regs
// fit 4 CTAs/SM = 16 warps/SM — attacking the issue-starvation that pinned
// rounds 5-8 at ~50-56% issue.

typedef unsigned long long u64;

namespace {
constexpr int kT     = 48;
constexpr int kF     = 16;
constexpr int kH     = 32;
constexpr int kTasks = 8192;             // 32768 batches / 4 per task
constexpr int kCTA   = 128;              // 4 warps
constexpr int kGrid  = 592;              // 4 CTAs/SM on 148 SMs, one wave
constexpr int kWarps = kGrid * (kCTA / 32);
}

__device__ __forceinline__ u64 pack2(float lo, float hi) {
    u64 r; asm("mov.b64 %0, {%1, %2};" : "=l"(r) : "f"(lo), "f"(hi)); return r;
}
__device__ __forceinline__ void unpack2(u64 v, float& lo, float& hi) {
    asm("mov.b64 {%0, %1}, %2;" : "=f"(lo), "=f"(hi) : "l"(v));
}
__device__ __forceinline__ u64 fma2(u64 a, u64 b, u64 c) {
    u64 d; asm("fma.rn.f32x2 %0, %1, %2, %3;" : "=l"(d) : "l"(a), "l"(b), "l"(c)); return d;
}
__device__ __forceinline__ float ex2a(float x) {
    float r; asm("ex2.approx.f32 %0, %1;" : "=f"(r) : "f"(x)); return r;
}
__device__ __forceinline__ float rcpa(float x) {
    float r; asm("rcp.approx.f32 %0, %1;" : "=f"(r) : "f"(x)); return r;
}
__device__ __forceinline__ float sig_fast(float x) {   // exact saturation at +/-inf
    return rcpa(1.0f + ex2a(-1.4426950408889634f * x));
}
__device__ __forceinline__ float tanh_fast(float x) {
    return fmaf(-2.0f, rcpa(1.0f + ex2a(2.8853900817779268f * x)), 1.0f);
}
__device__ __forceinline__ uint32_t smem_u32(const void* p) {
    return (uint32_t)__cvta_generic_to_shared(p);
}
__device__ __forceinline__ void sts128(uint32_t a, float x, float y, float z, float w) {
    asm volatile("st.shared.v4.f32 [%0], {%1,%2,%3,%4};"
                 :: "r"(a), "f"(x), "f"(y), "f"(z), "f"(w));
}
__device__ __forceinline__ void lds128(uint32_t a, u64& x, u64& y) {
    asm volatile("ld.shared.v2.u64 {%0,%1}, [%2];" : "=l"(x), "=l"(y) : "r"(a));
}
__device__ __forceinline__ float redsum(float v) {   // xor butterfly, all lanes get sum
#pragma unroll
    for (int m = 16; m >= 1; m >>= 1) v += __shfl_xor_sync(0xffffffffu, v, m);
    return v;
}

__global__ void __launch_bounds__(kCTA, 4)
gru_decoder_kernel(const float* __restrict__ feat,      // [B,T,F]
                   const float* __restrict__ init_in,   // [B,1]
                   const float* __restrict__ init_h,    // [B,H]
                   const float* __restrict__ kern,      // [1+F, 3H]
                   const float* __restrict__ rker,      // [H, 3H]
                   const float* __restrict__ bx,        // [3H]
                   const float* __restrict__ bh,        // [3H]
                   const float* __restrict__ dw,        // [H,1]
                   const float* __restrict__ db,        // [1]
                   float* __restrict__ out)             // [B,T,1]
{
    // Constant weight tables (per-lane-distinct reads, 128B rows -> 1 wf):
    // sWin[g][k][j] = kern[k][g*32+j]  (k=0: prev_out row; k=1..16: features)
    // sRz/sRr/sRh[k][j] = rker[k][g*32+j] for gate g = z/r/h
    __shared__ float sWin[3][17][kH];
    __shared__ float sRz[kH][kH], sRr[kH][kH], sRh[kH][kH];
    // Per-warp broadcast buffers, double-buffered:
    // shH[w][buf][j] = {hA0,hA1,hB0,hB1} of lane j
    // shX[w][buf][k] = {fA0,fA1,fB0,fB1} of feature k
    __shared__ __align__(16) float shH[4][2][kH][4];
    __shared__ __align__(16) float shX[4][2][kF][4];

    const int tid  = threadIdx.x;
    const int wip  = tid >> 5;
    const int lane = tid & 31;

    for (int i = tid; i < 17 * 96; i += kCTA) {
        int k = i / 96, c = i % 96;
        sWin[c / kH][k][c % kH] = kern[i];
    }
    for (int i = tid; i < kH * 96; i += kCTA) {
        int k = i / 96, c = i % 96;
        float w = rker[i];
        int g = c / kH, j = c % kH;
        if (g == 0)      sRz[k][j] = w;
        else if (g == 1) sRr[k][j] = w;
        else             sRh[k][j] = w;
    }
    __syncthreads();

    const float bzv = bx[lane] + bh[lane];
    const float brv = bx[kH + lane] + bh[kH + lane];
    const u64 bz2 = pack2(bzv, bzv);
    const u64 br2 = pack2(brv, brv);
    const u64 bx2 = pack2(bx[2 * kH + lane], bx[2 * kH + lane]);
    const u64 bh2 = pack2(bh[2 * kH + lane], bh[2 * kH + lane]);
    const float dwl = dw[lane];
    const float dbv = db[0];

    const uint32_t baseH = smem_u32(&shH[wip][0][0][0]);
    const uint32_t baseX = smem_u32(&shX[wip][0][0][0]);

    const int wg = (blockIdx.x * kCTA + tid) >> 5;

#pragma unroll 1
    for (int task = wg; task < kTasks; task += kWarps) {
        const int b0 = 4 * task, b1 = b0 + 1, b2 = b0 + 2, b3 = b0 + 3;

        float hA0 = init_h[(size_t)b0 * kH + lane];
        float hA1 = init_h[(size_t)b1 * kH + lane];
        float hB0 = init_h[(size_t)b2 * kH + lane];
        float hB1 = init_h[(size_t)b3 * kH + lane];
        u64 prevA = pack2(init_in[b0], init_in[b1]);
        u64 prevB = pack2(init_in[b2], init_in[b3]);

        const float* f0 = feat + (size_t)b0 * kT * kF;
        const float* f1 = feat + (size_t)b1 * kT * kF;
        const float* f2 = feat + (size_t)b2 * kT * kF;
        const float* f3 = feat + (size_t)b3 * kT * kF;
        float* ob = out + (size_t)b0 * kT;

        float fv0 = 0.f, fv1 = 0.f, fv2 = 0.f, fv3 = 0.f;
        if (lane < kF) {
            fv0 = f0[lane]; fv1 = f1[lane]; fv2 = f2[lane]; fv3 = f3[lane];
        }

#pragma unroll 1
        for (int t = 0; t < kT; t++) {
            const uint32_t bufH = baseH + (uint32_t)(t & 1) * (kH * 16);
            const uint32_t bufX = baseX + (uint32_t)(t & 1) * (kF * 16);

            // Publish my state + staged features.
            sts128(bufH + lane * 16, hA0, hA1, hB0, hB1);
            if (lane < kF) sts128(bufX + lane * 16, fv0, fv1, fv2, fv3);
            __syncwarp();

            // Next step's features (latency covered by the mainloop).
            if (lane < kF) {
                int tn = (t + 1 < kT) ? t + 1 : t;
                fv0 = f0[tn * kF + lane]; fv1 = f1[tn * kF + lane];
                fv2 = f2[tn * kF + lane]; fv3 = f3[tn * kF + lane];
            }

            u64 azA = bz2, azB = bz2;
            u64 arA = br2, arB = br2;
            u64 axA = bx2, axB = bx2;
            u64 ahA = bh2, ahB = bh2;

            // Recurrent part: broadcast LDS for h; weights per-lane from shared.
#pragma unroll
            for (int k = 0; k < kH; k++) {
                u64 hkA, hkB;
                lds128(bufH + k * 16, hkA, hkB);
                float rz = sRz[k][lane];
                float rr = sRr[k][lane];
                float rh = sRh[k][lane];
                u64 wz = pack2(rz, rz);
                u64 wr = pack2(rr, rr);
                u64 wh = pack2(rh, rh);
                azA = fma2(hkA, wz, azA); azB = fma2(hkB, wz, azB);
                arA = fma2(hkA, wr, arA); arB = fma2(hkB, wr, arB);
                ahA = fma2(hkA, wh, ahA); ahB = fma2(hkB, wh, ahB);
            }
            // prev_out term (weights row 0 from shared).
            {
                float w0 = sWin[0][0][lane];
                float w1 = sWin[1][0][lane];
                float w2 = sWin[2][0][lane];
                u64 wz = pack2(w0, w0);
                u64 wr = pack2(w1, w1);
                u64 wx = pack2(w2, w2);
                azA = fma2(prevA, wz, azA); azB = fma2(prevB, wz, azB);
                arA = fma2(prevA, wr, arA); arB = fma2(prevB, wr, arB);
                axA = fma2(prevA, wx, axA); axB = fma2(prevB, wx, axB);
            }
            // Feature part: broadcast LDS for x; weights per-lane from shared.
#pragma unroll
            for (int k = 0; k < kF; k++) {
                u64 xkA, xkB;
                lds128(bufX + k * 16, xkA, xkB);
                float w0 = sWin[0][k + 1][lane];
                float w1 = sWin[1][k + 1][lane];
                float w2 = sWin[2][k + 1][lane];
                u64 wz = pack2(w0, w0);
                u64 wr = pack2(w1, w1);
                u64 wx = pack2(w2, w2);
                azA = fma2(xkA, wz, azA); azB = fma2(xkB, wz, azB);
                arA = fma2(xkA, wr, arA); arB = fma2(xkB, wr, arB);
                axA = fma2(xkA, wx, axA); axB = fma2(xkB, wx, axB);
            }

            // Activations + state update.
            float z0, z1, r0, r1, x0, x1, g0, g1;
            unpack2(azA, z0, z1); unpack2(arA, r0, r1);
            unpack2(axA, x0, x1); unpack2(ahA, g0, g1);
            z0 = sig_fast(z0); z1 = sig_fast(z1);
            r0 = sig_fast(r0); r1 = sig_fast(r1);
            float hh0 = tanh_fast(fmaf(r0, g0, x0));
            float hh1 = tanh_fast(fmaf(r1, g1, x1));
            hA0 = fmaf(z0, hA0 - hh0, hh0);
            hA1 = fmaf(z1, hA1 - hh1, hh1);

            unpack2(azB, z0, z1); unpack2(arB, r0, r1);
            unpack2(axB, x0, x1); unpack2(ahB, g0, g1);
            z0 = sig_fast(z0); z1 = sig_fast(z1);
            r0 = sig_fast(r0); r1 = sig_fast(r1);
            hh0 = tanh_fast(fmaf(r0, g0, x0));
            hh1 = tanh_fast(fmaf(r1, g1, x1));
            hB0 = fmaf(z0, hB0 - hh0, hh0);
            hB1 = fmaf(z1, hB1 - hh1, hh1);

            // Dense(1): butterfly-reduce; every lane ends with the sums.
            float oA0 = redsum(hA0 * dwl) + dbv;
            float oA1 = redsum(hA1 * dwl) + dbv;
            float oB0 = redsum(hB0 * dwl) + dbv;
            float oB1 = redsum(hB1 * dwl) + dbv;
            prevA = pack2(oA0, oA1);
            prevB = pack2(oB0, oB1);
            if (lane == 0) {
                ob[t]          = oA0;
                ob[kT + t]     = oA1;
                ob[2 * kT + t] = oB0;
                ob[3 * kT + t] = oB1;
            }
        }
    }
}

extern "C" void kernel_launch(void* const* d_in, const int* in_sizes, int n_in,
                              void* d_out, int out_size) {
    (void)in_sizes; (void)n_in; (void)out_size;
    gru_decoder_kernel<<<kGrid, kCTA>>>(
        (const float*)d_in[0],   // decoder_feature
        (const float*)d_in[1],   // decoder_init_input
        (const float*)d_in[2],   // init_state
        (const float*)d_in[3],   // kernel
        (const float*)d_in[4],   // recurrent_kernel
        (const float*)d_in[5],   // bias_x
        (const float*)d_in[6],   // bias_h
        (const float*)d_in[7],   // dense_w
        (const float*)d_in[8],   // dense_b
        (float*)d_out);
}

// round 10
// speedup vs baseline: 1.0585x; 1.0585x over previous
#include <cuda_runtime.h>
#include <cstdint>

// GRU decoder (Keras reset_after=True), B=32768, T=48, F=16, H=32, fp32.
// R8 structure (batch-packed f32x2, lane j = neuron j, 4 batches/warp as two
// pairs, h broadcast via per-warp shared buffer; Rz/Rr register-stationary,
// Rh + input weights in shared). Change vs R8: features are read DIRECTLY
// from global as uniform LDG.128 (1 wavefront) instead of the
// LDG->STS->LDS.128 broadcast round trip — cuts ~16% of the L1/MIO
// wavefronts that R8/R9 showed to be the binding pipe.

typedef unsigned long long u64;

namespace {
constexpr int kT     = 48;
constexpr int kF     = 16;
constexpr int kH     = 32;
constexpr int kTasks = 8192;             // 32768 batches / 4 per task
constexpr int kCTA   = 128;              // 4 warps
constexpr int kGrid  = 444;              // 3 CTAs/SM on 148 SMs, one wave
constexpr int kWarps = kGrid * (kCTA / 32);
}

__device__ __forceinline__ u64 pack2(float lo, float hi) {
    u64 r; asm("mov.b64 %0, {%1, %2};" : "=l"(r) : "f"(lo), "f"(hi)); return r;
}
__device__ __forceinline__ void unpack2(u64 v, float& lo, float& hi) {
    asm("mov.b64 {%0, %1}, %2;" : "=f"(lo), "=f"(hi) : "l"(v));
}
__device__ __forceinline__ u64 fma2(u64 a, u64 b, u64 c) {
    u64 d; asm("fma.rn.f32x2 %0, %1, %2, %3;" : "=l"(d) : "l"(a), "l"(b), "l"(c)); return d;
}
__device__ __forceinline__ float ex2a(float x) {
    float r; asm("ex2.approx.f32 %0, %1;" : "=f"(r) : "f"(x)); return r;
}
__device__ __forceinline__ float rcpa(float x) {
    float r; asm("rcp.approx.f32 %0, %1;" : "=f"(r) : "f"(x)); return r;
}
__device__ __forceinline__ float sig_fast(float x) {   // exact saturation at +/-inf
    return rcpa(1.0f + ex2a(-1.4426950408889634f * x));
}
__device__ __forceinline__ float tanh_fast(float x) {
    return fmaf(-2.0f, rcpa(1.0f + ex2a(2.8853900817779268f * x)), 1.0f);
}
__device__ __forceinline__ uint32_t smem_u32(const void* p) {
    return (uint32_t)__cvta_generic_to_shared(p);
}
__device__ __forceinline__ void sts128(uint32_t a, float x, float y, float z, float w) {
    asm volatile("st.shared.v4.f32 [%0], {%1,%2,%3,%4};"
                 :: "r"(a), "f"(x), "f"(y), "f"(z), "f"(w));
}
__device__ __forceinline__ void lds128(uint32_t a, u64& x, u64& y) {
    asm volatile("ld.shared.v2.u64 {%0,%1}, [%2];" : "=l"(x), "=l"(y) : "r"(a));
}
__device__ __forceinline__ void prefetchL2(const void* p) {
    asm volatile("prefetch.global.L2 [%0];" :: "l"(p));
}
__device__ __forceinline__ float redsum(float v) {   // xor butterfly, all lanes get sum
#pragma unroll
    for (int m = 16; m >= 1; m >>= 1) v += __shfl_xor_sync(0xffffffffu, v, m);
    return v;
}

__global__ void __launch_bounds__(kCTA, 3)
gru_decoder_kernel(const float* __restrict__ feat,      // [B,T,F]
                   const float* __restrict__ init_in,   // [B,1]
                   const float* __restrict__ init_h,    // [B,H]
                   const float* __restrict__ kern,      // [1+F, 3H]
                   const float* __restrict__ rker,      // [H, 3H]
                   const float* __restrict__ bx,        // [3H]
                   const float* __restrict__ bh,        // [3H]
                   const float* __restrict__ dw,        // [H,1]
                   const float* __restrict__ db,        // [1]
                   float* __restrict__ out)             // [B,T,1]
{
    // Constant weight tables (per-lane-distinct reads, 128B rows -> 1 wf):
    // sWin[g][k][j] = kern[k][g*32+j]  (k=0: prev_out row; k=1..16: features)
    // sRh[k][j]     = rker[k][64+j]    (hh-gate recurrent)
    __shared__ float sWin[3][17][kH];
    __shared__ float sRh[kH][kH];
    // Per-warp h broadcast buffer, double-buffered:
    // shH[w][buf][j] = {hA0,hA1,hB0,hB1} of lane j
    __shared__ __align__(16) float shH[4][2][kH][4];

    const int tid  = threadIdx.x;
    const int wip  = tid >> 5;
    const int lane = tid & 31;

    for (int i = tid; i < 17 * 96; i += kCTA) {
        int k = i / 96, c = i % 96;
        sWin[c / kH][k][c % kH] = kern[i];
    }
    for (int i = tid; i < kH * kH; i += kCTA) {
        int k = i / kH, j = i % kH;
        sRh[k][j] = rker[k * 96 + 2 * kH + j];
    }
    __syncthreads();

    // Register-stationary recurrent weights for z and r gates.
    float Rz[kH], Rr[kH];
#pragma unroll
    for (int k = 0; k < kH; k++) {
        Rz[k] = rker[k * 96 + lane];
        Rr[k] = rker[k * 96 + kH + lane];
    }
    const float bzv = bx[lane] + bh[lane];
    const float brv = bx[kH + lane] + bh[kH + lane];
    const u64 bz2 = pack2(bzv, bzv);
    const u64 br2 = pack2(brv, brv);
    const u64 bx2 = pack2(bx[2 * kH + lane], bx[2 * kH + lane]);
    const u64 bh2 = pack2(bh[2 * kH + lane], bh[2 * kH + lane]);
    const float dwl = dw[lane];
    const float dbv = db[0];

    const uint32_t baseH = smem_u32(&shH[wip][0][0][0]);

    const int wg = (blockIdx.x * kCTA + tid) >> 5;

#pragma unroll 1
    for (int task = wg; task < kTasks; task += kWarps) {
        const int b0 = 4 * task, b1 = b0 + 1, b2 = b0 + 2, b3 = b0 + 3;

        float hA0 = init_h[(size_t)b0 * kH + lane];
        float hA1 = init_h[(size_t)b1 * kH + lane];
        float hB0 = init_h[(size_t)b2 * kH + lane];
        float hB1 = init_h[(size_t)b3 * kH + lane];
        u64 prevA = pack2(init_in[b0], init_in[b1]);
        u64 prevB = pack2(init_in[b2], init_in[b3]);

        const float4* fp0 = reinterpret_cast<const float4*>(feat + (size_t)b0 * kT * kF);
        const float4* fp1 = reinterpret_cast<const float4*>(feat + (size_t)b1 * kT * kF);
        const float4* fp2 = reinterpret_cast<const float4*>(feat + (size_t)b2 * kT * kF);
        const float4* fp3 = reinterpret_cast<const float4*>(feat + (size_t)b3 * kT * kF);
        float* ob = out + (size_t)b0 * kT;

        // Warm L2 for the first step's feature lines.
        prefetchL2(fp0); prefetchL2(fp1); prefetchL2(fp2); prefetchL2(fp3);

#pragma unroll 1
        for (int t = 0; t < kT; t++) {
            const uint32_t bufH = baseH + (uint32_t)(t & 1) * (kH * 16);

            // Publish my state.
            sts128(bufH + lane * 16, hA0, hA1, hB0, hB1);
            __syncwarp();

            // Prefetch next step's feature lines into L2 (read-once data).
            if (t + 1 < kT) {
                prefetchL2(fp0 + (t + 1) * 4); prefetchL2(fp1 + (t + 1) * 4);
                prefetchL2(fp2 + (t + 1) * 4); prefetchL2(fp3 + (t + 1) * 4);
            }

            u64 azA = bz2, azB = bz2;
            u64 arA = br2, arB = br2;
            u64 axA = bx2, axB = bx2;
            u64 ahA = bh2, ahB = bh2;

            // Recurrent part: broadcast LDS for h; Rz/Rr dup'd from RF,
            // Rh read per-lane from shared.
#pragma unroll
            for (int k = 0; k < kH; k++) {
                u64 hkA, hkB;
                lds128(bufH + k * 16, hkA, hkB);
                u64 wz = pack2(Rz[k], Rz[k]);
                u64 wr = pack2(Rr[k], Rr[k]);
                float rh = sRh[k][lane];
                u64 wh = pack2(rh, rh);
                azA = fma2(hkA, wz, azA); azB = fma2(hkB, wz, azB);
                arA = fma2(hkA, wr, arA); arB = fma2(hkB, wr, arB);
                ahA = fma2(hkA, wh, ahA); ahB = fma2(hkB, wh, ahB);
            }
            // prev_out term (weights row 0 from shared).
            {
                float w0 = sWin[0][0][lane];
                float w1 = sWin[1][0][lane];
                float w2 = sWin[2][0][lane];
                u64 wz = pack2(w0, w0);
                u64 wr = pack2(w1, w1);
                u64 wx = pack2(w2, w2);
                azA = fma2(prevA, wz, azA); azB = fma2(prevB, wz, azB);
                arA = fma2(prevA, wr, arA); arB = fma2(prevB, wr, arB);
                axA = fma2(prevA, wx, axA); axB = fma2(prevB, wx, axB);
            }
            // Feature part: uniform LDG.128 per batch (1 wavefront each), no
            // shared staging. ptxas hoists these independent loads early.
#pragma unroll
            for (int q = 0; q < 4; q++) {
                float4 a = __ldg(fp0 + t * 4 + q);
                float4 b = __ldg(fp1 + t * 4 + q);
                float4 c = __ldg(fp2 + t * 4 + q);
                float4 d = __ldg(fp3 + t * 4 + q);
                const float* ea = &a.x;
                const float* eb = &b.x;
                const float* ec = &c.x;
                const float* ed = &d.x;
#pragma unroll
                for (int e = 0; e < 4; e++) {
                    int k = 4 * q + e;
                    u64 xA = pack2(ea[e], eb[e]);
                    u64 xB = pack2(ec[e], ed[e]);
                    float w0 = sWin[0][k + 1][lane];
                    float w1 = sWin[1][k + 1][lane];
                    float w2 = sWin[2][k + 1][lane];
                    u64 wz = pack2(w0, w0);
                    u64 wr = pack2(w1, w1);
                    u64 wx = pack2(w2, w2);
                    azA = fma2(xA, wz, azA); azB = fma2(xB, wz, azB);
                    arA = fma2(xA, wr, arA); arB = fma2(xB, wr, arB);
                    axA = fma2(xA, wx, axA); axB = fma2(xB, wx, axB);
                }
            }

            // Activations + state update.
            float z0, z1, r0, r1, x0, x1, g0, g1;
            unpack2(azA, z0, z1); unpack2(arA, r0, r1);
            unpack2(axA, x0, x1); unpack2(ahA, g0, g1);
            z0 = sig_fast(z0); z1 = sig_fast(z1);
            r0 = sig_fast(r0); r1 = sig_fast(r1);
            float hh0 = tanh_fast(fmaf(r0, g0, x0));
            float hh1 = tanh_fast(fmaf(r1, g1, x1));
            hA0 = fmaf(z0, hA0 - hh0, hh0);
            hA1 = fmaf(z1, hA1 - hh1, hh1);

            unpack2(azB, z0, z1); unpack2(arB, r0, r1);
            unpack2(axB, x0, x1); unpack2(ahB, g0, g1);
            z0 = sig_fast(z0); z1 = sig_fast(z1);
            r0 = sig_fast(r0); r1 = sig_fast(r1);
            hh0 = tanh_fast(fmaf(r0, g0, x0));
            hh1 = tanh_fast(fmaf(r1, g1, x1));
            hB0 = fmaf(z0, hB0 - hh0, hh0);
            hB1 = fmaf(z1, hB1 - hh1, hh1);

            // Dense(1): butterfly-reduce; every lane ends with the sums.
            float oA0 = redsum(hA0 * dwl) + dbv;
            float oA1 = redsum(hA1 * dwl) + dbv;
            float oB0 = redsum(hB0 * dwl) + dbv;
            float oB1 = redsum(hB1 * dwl) + dbv;
            prevA = pack2(oA0, oA1);
            prevB = pack2(oB0, oB1);
            if (lane == 0) {
                ob[t]          = oA0;
                ob[kT + t]     = oA1;
                ob[2 * kT + t] = oB0;
                ob[3 * kT + t] = oB1;
            }
        }
    }
}

extern "C" void kernel_launch(void* const* d_in, const int* in_sizes, int n_in,
                              void* d_out, int out_size) {
    (void)in_sizes; (void)n_in; (void)out_size;
    gru_decoder_kernel<<<kGrid, kCTA>>>(
        (const float*)d_in[0],   // decoder_feature
        (const float*)d_in[1],   // decoder_init_input
        (const float*)d_in[2],   // init_state
        (const float*)d_in[3],   // kernel
        (const float*)d_in[4],   // recurrent_kernel
        (const float*)d_in[5],   // bias_x
        (const float*)d_in[6],   // bias_h
        (const float*)d_in[7],   // dense_w
        (const float*)d_in[8],   // dense_b
        (float*)d_out);
}

// round 11
// speedup vs baseline: 1.1062x; 1.0451x over previous
#include <cuda_runtime.h>
#include <cstdint>

// GRU decoder (Keras reset_after=True), B=32768, T=48, F=16, H=32, fp32.
// Lane j owns neuron j; f32x2 lanes = 2 batch elements; each warp processes
// EIGHT batches (4 pairs) per task so the per-lane weight reads (Rh + input
// kernel from shared, 83 wavefronts) amortize over 2x the math — making the
// fma pipe, not the L1/MIO crossbar, the binding resource (R8-R10 evidence).
// h/x broadcast rows are 48B-padded so the per-lane sts128 publishes are
// conflict-free. Tasks are work-stolen via a global atomic (reset kernel
// first; both launches graph-capturable, no allocation).

typedef unsigned long long u64;

namespace {
constexpr int kT      = 48;
constexpr int kF      = 16;
constexpr int kH      = 32;
constexpr int kBat    = 8;               // batches per task
constexpr int kTasks  = 32768 / kBat;    // 4096
constexpr int kCTA    = 128;             // 4 warps
constexpr int kGrid   = 296;             // 2 CTAs/SM on 148 SMs
}

__device__ int g_task_counter;

__global__ void reset_counter_kernel() { g_task_counter = 0; }

__device__ __forceinline__ u64 pack2(float lo, float hi) {
    u64 r; asm("mov.b64 %0, {%1, %2};" : "=l"(r) : "f"(lo), "f"(hi)); return r;
}
__device__ __forceinline__ void unpack2(u64 v, float& lo, float& hi) {
    asm("mov.b64 {%0, %1}, %2;" : "=f"(lo), "=f"(hi) : "l"(v));
}
__device__ __forceinline__ u64 fma2(u64 a, u64 b, u64 c) {
    u64 d; asm("fma.rn.f32x2 %0, %1, %2, %3;" : "=l"(d) : "l"(a), "l"(b), "l"(c)); return d;
}
__device__ __forceinline__ float ex2a(float x) {
    float r; asm("ex2.approx.f32 %0, %1;" : "=f"(r) : "f"(x)); return r;
}
__device__ __forceinline__ float rcpa(float x) {
    float r; asm("rcp.approx.f32 %0, %1;" : "=f"(r) : "f"(x)); return r;
}
__device__ __forceinline__ float sig_fast(float x) {   // exact saturation at +/-inf
    return rcpa(1.0f + ex2a(-1.4426950408889634f * x));
}
__device__ __forceinline__ float tanh_fast(float x) {
    return fmaf(-2.0f, rcpa(1.0f + ex2a(2.8853900817779268f * x)), 1.0f);
}
__device__ __forceinline__ uint32_t smem_u32(const void* p) {
    return (uint32_t)__cvta_generic_to_shared(p);
}
__device__ __forceinline__ void sts128(uint32_t a, float x, float y, float z, float w) {
    asm volatile("st.shared.v4.f32 [%0], {%1,%2,%3,%4};"
                 :: "r"(a), "f"(x), "f"(y), "f"(z), "f"(w));
}
__device__ __forceinline__ void lds128(uint32_t a, u64& x, u64& y) {
    asm volatile("ld.shared.v2.u64 {%0,%1}, [%2];" : "=l"(x), "=l"(y) : "r"(a));
}
__device__ __forceinline__ float redsum(float v) {   // xor butterfly, all lanes get sum
#pragma unroll
    for (int m = 16; m >= 1; m >>= 1) v += __shfl_xor_sync(0xffffffffu, v, m);
    return v;
}

__global__ void __launch_bounds__(kCTA, 2)
gru_decoder_kernel(const float* __restrict__ feat,      // [B,T,F]
                   const float* __restrict__ init_in,   // [B,1]
                   const float* __restrict__ init_h,    // [B,H]
                   const float* __restrict__ kern,      // [1+F, 3H]
                   const float* __restrict__ rker,      // [H, 3H]
                   const float* __restrict__ bx,        // [3H]
                   const float* __restrict__ bh,        // [3H]
                   const float* __restrict__ dw,        // [H,1]
                   const float* __restrict__ db,        // [1]
                   float* __restrict__ out)             // [B,T,1]
{
    // Constant weight tables (per-lane-distinct reads, 128B rows -> 1 wf):
    __shared__ float sWin[3][17][kH];      // kern: k=0 prev row, 1..16 features
    __shared__ float sRh[kH][kH];          // hh-gate recurrent
    // Per-warp broadcast buffers, double-buffered, 48B-padded rows
    // (12 floats; first 8 used) so per-lane 2xSTS128 publish is conflict-free.
    __shared__ __align__(16) float shH[4][2][kH][12];
    __shared__ __align__(16) float shX[4][2][kF][12];

    const int tid  = threadIdx.x;
    const int wip  = tid >> 5;
    const int lane = tid & 31;

    for (int i = tid; i < 17 * 96; i += kCTA) {
        int k = i / 96, c = i % 96;
        sWin[c / kH][k][c % kH] = kern[i];
    }
    for (int i = tid; i < kH * kH; i += kCTA) {
        int k = i / kH, j = i % kH;
        sRh[k][j] = rker[k * 96 + 2 * kH + j];
    }
    __syncthreads();

    // Register-stationary recurrent weights for z and r gates.
    float Rz[kH], Rr[kH];
#pragma unroll
    for (int k = 0; k < kH; k++) {
        Rz[k] = rker[k * 96 + lane];
        Rr[k] = rker[k * 96 + kH + lane];
    }
    const float bzv = bx[lane] + bh[lane];
    const float brv = bx[kH + lane] + bh[kH + lane];
    const u64 bz2 = pack2(bzv, bzv);
    const u64 br2 = pack2(brv, brv);
    const u64 bx2 = pack2(bx[2 * kH + lane], bx[2 * kH + lane]);
    const u64 bh2 = pack2(bh[2 * kH + lane], bh[2 * kH + lane]);
    const float dwl = dw[lane];
    const float dbv = db[0];
    const float Wz0 = kern[lane];              // prev_out row of kern
    const float Wr0 = kern[kH + lane];
    const float Wx0 = kern[2 * kH + lane];

    const uint32_t baseH = smem_u32(&shH[wip][0][0][0]);
    const uint32_t baseX = smem_u32(&shX[wip][0][0][0]);

    for (;;) {
        int task;
        if (lane == 0) task = atomicAdd(&g_task_counter, 1);
        task = __shfl_sync(0xffffffffu, task, 0);
        if (task >= kTasks) break;

        const int b0 = kBat * task;
        const float* fbase = feat + (size_t)b0 * kT * kF;   // rows i*768 apart
        float* ob = out + (size_t)b0 * kT;

        float h[kBat], op[kBat], fv[kBat];
#pragma unroll
        for (int i = 0; i < kBat; i++) {
            h[i]  = init_h[(size_t)(b0 + i) * kH + lane];
            op[i] = init_in[b0 + i];
            fv[i] = 0.0f;
            if (lane < kF) fv[i] = fbase[i * (kT * kF) + lane];
        }

#pragma unroll 1
        for (int t = 0; t < kT; t++) {
            const uint32_t bufH = baseH + (uint32_t)(t & 1) * (kH * 48);
            const uint32_t bufX = baseX + (uint32_t)(t & 1) * (kF * 48);

            // Publish my neuron's state (8 batches) + staged features.
            sts128(bufH + (uint32_t)lane * 48,      h[0], h[1], h[2], h[3]);
            sts128(bufH + (uint32_t)lane * 48 + 16, h[4], h[5], h[6], h[7]);
            if (lane < kF) {
                sts128(bufX + (uint32_t)lane * 48,      fv[0], fv[1], fv[2], fv[3]);
                sts128(bufX + (uint32_t)lane * 48 + 16, fv[4], fv[5], fv[6], fv[7]);
            }
            __syncwarp();

            // Previous step's output (o_{t-1} = dw.h_{t-1} + db): the 5-SHFL
            // chains issue here and complete under the GEMM below.
            if (t > 0) {
#pragma unroll
                for (int i = 0; i < kBat; i++) {
                    float o = redsum(h[i] * dwl) + dbv;
                    op[i] = o;
                    if (lane == 0) ob[i * kT + (t - 1)] = o;
                }
            }

            // Load next step's features (used at t+1; ~full step of slack).
            if (lane < kF) {
                int tn = (t + 1 < kT) ? t + 1 : t;
#pragma unroll
                for (int i = 0; i < kBat; i++)
                    fv[i] = fbase[i * (kT * kF) + tn * kF + lane];
            }

            // Accumulators: 4 pairs x 4 gates.
            u64 az[4], ar[4], ah[4], ax[4];
#pragma unroll
            for (int p = 0; p < 4; p++) {
                az[p] = bz2; ar[p] = br2; ah[p] = bh2; ax[p] = bx2;
            }

            // Recurrent part: 2 uniform lds128 per k deliver all 4 pairs.
#pragma unroll
            for (int k = 0; k < kH; k++) {
                u64 p0, p1, p2, p3;
                lds128(bufH + (uint32_t)k * 48,      p0, p1);
                lds128(bufH + (uint32_t)k * 48 + 16, p2, p3);
                u64 wz = pack2(Rz[k], Rz[k]);
                u64 wr = pack2(Rr[k], Rr[k]);
                float rh = sRh[k][lane];
                u64 wh = pack2(rh, rh);
                az[0] = fma2(p0, wz, az[0]); az[1] = fma2(p1, wz, az[1]);
                az[2] = fma2(p2, wz, az[2]); az[3] = fma2(p3, wz, az[3]);
                ar[0] = fma2(p0, wr, ar[0]); ar[1] = fma2(p1, wr, ar[1]);
                ar[2] = fma2(p2, wr, ar[2]); ar[3] = fma2(p3, wr, ar[3]);
                ah[0] = fma2(p0, wh, ah[0]); ah[1] = fma2(p1, wh, ah[1]);
                ah[2] = fma2(p2, wh, ah[2]); ah[3] = fma2(p3, wh, ah[3]);
            }
            // Feature part.
#pragma unroll
            for (int k = 0; k < kF; k++) {
                u64 p0, p1, p2, p3;
                lds128(bufX + (uint32_t)k * 48,      p0, p1);
                lds128(bufX + (uint32_t)k * 48 + 16, p2, p3);
                float w0 = sWin[0][k + 1][lane];
                float w1 = sWin[1][k + 1][lane];
                float w2 = sWin[2][k + 1][lane];
                u64 wz = pack2(w0, w0);
                u64 wr = pack2(w1, w1);
                u64 wx = pack2(w2, w2);
                az[0] = fma2(p0, wz, az[0]); az[1] = fma2(p1, wz, az[1]);
                az[2] = fma2(p2, wz, az[2]); az[3] = fma2(p3, wz, az[3]);
                ar[0] = fma2(p0, wr, ar[0]); ar[1] = fma2(p1, wr, ar[1]);
                ar[2] = fma2(p2, wr, ar[2]); ar[3] = fma2(p3, wr, ar[3]);
                ax[0] = fma2(p0, wx, ax[0]); ax[1] = fma2(p1, wx, ax[1]);
                ax[2] = fma2(p2, wx, ax[2]); ax[3] = fma2(p3, wx, ax[3]);
            }

            // Epilogue: prev-out terms (scalar, off the GEMM path) +
            // activations + state update, per batch.
#pragma unroll
            for (int p = 0; p < 4; p++) {
                float azl, azh, arl, arh, axl, axh, ahl, ahh;
                unpack2(az[p], azl, azh);
                unpack2(ar[p], arl, arh);
                unpack2(ax[p], axl, axh);
                unpack2(ah[p], ahl, ahh);
                {
                    int i = 2 * p;
                    float z = sig_fast(fmaf(Wz0, op[i], azl));
                    float r = sig_fast(fmaf(Wr0, op[i], arl));
                    float hh = tanh_fast(fmaf(r, ahl, fmaf(Wx0, op[i], axl)));
                    h[i] = fmaf(z, h[i] - hh, hh);
                }
                {
                    int i = 2 * p + 1;
                    float z = sig_fast(fmaf(Wz0, op[i], azh));
                    float r = sig_fast(fmaf(Wr0, op[i], arh));
                    float hh = tanh_fast(fmaf(r, ahh, fmaf(Wx0, op[i], axh)));
                    h[i] = fmaf(z, h[i] - hh, hh);
                }
            }
        }

        // Final outputs o_{T-1}.
#pragma unroll
        for (int i = 0; i < kBat; i++) {
            float o = redsum(h[i] * dwl) + dbv;
            if (lane == 0) ob[i * kT + (kT - 1)] = o;
        }
    }
}

extern "C" void kernel_launch(void* const* d_in, const int* in_sizes, int n_in,
                              void* d_out, int out_size) {
    (void)in_sizes; (void)n_in; (void)out_size;
    reset_counter_kernel<<<1, 1>>>();
    gru_decoder_kernel<<<kGrid, kCTA>>>(
        (const float*)d_in[0],   // decoder_feature
        (const float*)d_in[1],   // decoder_init_input
        (const float*)d_in[2],   // init_state
        (const float*)d_in[3],   // kernel
        (const float*)d_in[4],   // recurrent_kernel
        (const float*)d_in[5],   // bias_x
        (const float*)d_in[6],   // bias_h
        (const float*)d_in[7],   // dense_w
        (const float*)d_in[8],   // dense_b
        (float*)d_out);
}

// round 13
// speedup vs baseline: 1.1094x; 1.0028x over previous
#include <cuda_runtime.h>
#include <cstdint>

// GRU decoder (Keras reset_after=True), B=32768, T=48, F=16, H=32, fp32.
// Lane j owns neuron j; f32x2 lanes = 2 batch elements; each warp processes
// EIGHT batches (4 pairs) per task so the per-lane weight reads (Rh + input
// kernel from shared, 83 wavefronts) amortize over 2x the math — making the
// fma pipe, not the L1/MIO crossbar, the binding resource (R8-R10 evidence).
// h/x broadcast rows are 48B-padded so the per-lane sts128 publishes are
// conflict-free. Tasks are work-stolen via a global atomic (reset kernel
// first; both launches graph-capturable, no allocation).

typedef unsigned long long u64;

namespace {
constexpr int kT      = 48;
constexpr int kF      = 16;
constexpr int kH      = 32;
constexpr int kBat    = 8;               // batches per task
constexpr int kTasks  = 32768 / kBat;    // 4096
constexpr int kCTA    = 128;             // 4 warps
constexpr int kGrid   = 296;             // 2 CTAs/SM on 148 SMs
}

__device__ int g_task_counter;

__global__ void reset_counter_kernel() { g_task_counter = 0; }

__device__ __forceinline__ u64 pack2(float lo, float hi) {
    u64 r; asm("mov.b64 %0, {%1, %2};" : "=l"(r) : "f"(lo), "f"(hi)); return r;
}
__device__ __forceinline__ void unpack2(u64 v, float& lo, float& hi) {
    asm("mov.b64 {%0, %1}, %2;" : "=f"(lo), "=f"(hi) : "l"(v));
}
__device__ __forceinline__ u64 fma2(u64 a, u64 b, u64 c) {
    u64 d; asm("fma.rn.f32x2 %0, %1, %2, %3;" : "=l"(d) : "l"(a), "l"(b), "l"(c)); return d;
}
__device__ __forceinline__ float ex2a(float x) {
    float r; asm("ex2.approx.f32 %0, %1;" : "=f"(r) : "f"(x)); return r;
}
__device__ __forceinline__ float rcpa(float x) {
    float r; asm("rcp.approx.f32 %0, %1;" : "=f"(r) : "f"(x)); return r;
}
__device__ __forceinline__ float sig_fast(float x) {   // exact saturation at +/-inf
    return rcpa(1.0f + ex2a(-1.4426950408889634f * x));
}
__device__ __forceinline__ float tanh_fast(float x) {
    return fmaf(-2.0f, rcpa(1.0f + ex2a(2.8853900817779268f * x)), 1.0f);
}
__device__ __forceinline__ uint32_t smem_u32(const void* p) {
    return (uint32_t)__cvta_generic_to_shared(p);
}
__device__ __forceinline__ void sts128(uint32_t a, float x, float y, float z, float w) {
    asm volatile("st.shared.v4.f32 [%0], {%1,%2,%3,%4};"
                 :: "r"(a), "f"(x), "f"(y), "f"(z), "f"(w));
}
__device__ __forceinline__ void lds128(uint32_t a, u64& x, u64& y) {
    asm volatile("ld.shared.v2.u64 {%0,%1}, [%2];" : "=l"(x), "=l"(y) : "r"(a));
}
__device__ __forceinline__ float redsum(float v) {   // xor butterfly, all lanes get sum
#pragma unroll
    for (int m = 16; m >= 1; m >>= 1) v += __shfl_xor_sync(0xffffffffu, v, m);
    return v;
}

__global__ void __launch_bounds__(kCTA, 2)
gru_decoder_kernel(const float* __restrict__ feat,      // [B,T,F]
                   const float* __restrict__ init_in,   // [B,1]
                   const float* __restrict__ init_h,    // [B,H]
                   const float* __restrict__ kern,      // [1+F, 3H]
                   const float* __restrict__ rker,      // [H, 3H]
                   const float* __restrict__ bx,        // [3H]
                   const float* __restrict__ bh,        // [3H]
                   const float* __restrict__ dw,        // [H,1]
                   const float* __restrict__ db,        // [1]
                   float* __restrict__ out)             // [B,T,1]
{
    // Constant weight tables (per-lane-distinct reads, 128B rows -> 1 wf):
    __shared__ float sWin[3][17][kH];      // kern: k=0 prev row, 1..16 features
    __shared__ float sRh[kH][kH];          // hh-gate recurrent
    // Per-warp broadcast buffers, double-buffered, 48B-padded rows
    // (12 floats; first 8 used) so per-lane 2xSTS128 publish is conflict-free.
    __shared__ __align__(16) float shH[4][2][kH][12];
    __shared__ __align__(16) float shX[4][2][kF][12];

    const int tid  = threadIdx.x;
    const int wip  = tid >> 5;
    const int lane = tid & 31;

    for (int i = tid; i < 17 * 96; i += kCTA) {
        int k = i / 96, c = i % 96;
        sWin[c / kH][k][c % kH] = kern[i];
    }
    for (int i = tid; i < kH * kH; i += kCTA) {
        int k = i / kH, j = i % kH;
        sRh[k][j] = rker[k * 96 + 2 * kH + j];
    }
    __syncthreads();

    // Register-stationary recurrent weights for z and r gates.
    float Rz[kH], Rr[kH];
#pragma unroll
    for (int k = 0; k < kH; k++) {
        Rz[k] = rker[k * 96 + lane];
        Rr[k] = rker[k * 96 + kH + lane];
    }
    const float bzv = bx[lane] + bh[lane];
    const float brv = bx[kH + lane] + bh[kH + lane];
    const u64 bz2 = pack2(bzv, bzv);
    const u64 br2 = pack2(brv, brv);
    const u64 bx2 = pack2(bx[2 * kH + lane], bx[2 * kH + lane]);
    const u64 bh2 = pack2(bh[2 * kH + lane], bh[2 * kH + lane]);
    const float dwl = dw[lane];
    const float dbv = db[0];
    const float Wz0 = kern[lane];              // prev_out row of kern
    const float Wr0 = kern[kH + lane];
    const float Wx0 = kern[2 * kH + lane];

    const uint32_t baseH = smem_u32(&shH[wip][0][0][0]);
    const uint32_t baseX = smem_u32(&shX[wip][0][0][0]);

    for (;;) {
        int task;
        if (lane == 0) task = atomicAdd(&g_task_counter, 1);
        task = __shfl_sync(0xffffffffu, task, 0);
        if (task >= kTasks) break;

        const int b0 = kBat * task;
        const float* fbase = feat + (size_t)b0 * kT * kF;   // rows i*768 apart
        float* ob = out + (size_t)b0 * kT;

        float h[kBat], op[kBat], fv[kBat];
#pragma unroll
        for (int i = 0; i < kBat; i++) {
            h[i]  = init_h[(size_t)(b0 + i) * kH + lane];
            op[i] = init_in[b0 + i];
            fv[i] = 0.0f;
            if (lane < kF) fv[i] = fbase[i * (kT * kF) + lane];
        }

#pragma unroll 1
        for (int t = 0; t < kT; t++) {
            const uint32_t bufH = baseH + (uint32_t)(t & 1) * (kH * 48);
            const uint32_t bufX = baseX + (uint32_t)(t & 1) * (kF * 48);

            // Publish my neuron's state (8 batches) + staged features.
            sts128(bufH + (uint32_t)lane * 48,      h[0], h[1], h[2], h[3]);
            sts128(bufH + (uint32_t)lane * 48 + 16, h[4], h[5], h[6], h[7]);
            if (lane < kF) {
                sts128(bufX + (uint32_t)lane * 48,      fv[0], fv[1], fv[2], fv[3]);
                sts128(bufX + (uint32_t)lane * 48 + 16, fv[4], fv[5], fv[6], fv[7]);
            }
            __syncwarp();

            // Previous step's output (o_{t-1} = dw.h_{t-1} + db): the 5-SHFL
            // chains issue here and complete under the GEMM below.
            if (t > 0) {
#pragma unroll
                for (int i = 0; i < kBat; i++) {
                    float o = redsum(h[i] * dwl) + dbv;
                    op[i] = o;
                    if (lane == 0) ob[i * kT + (t - 1)] = o;
                }
            }

            // Load next step's features (used at t+1; ~full step of slack).
            if (lane < kF) {
                int tn = (t + 1 < kT) ? t + 1 : t;
#pragma unroll
                for (int i = 0; i < kBat; i++)
                    fv[i] = fbase[i * (kT * kF) + tn * kF + lane];
            }

            // Accumulators: 4 pairs x 4 gates.
            u64 az[4], ar[4], ah[4], ax[4];
#pragma unroll
            for (int p = 0; p < 4; p++) {
                az[p] = bz2; ar[p] = br2; ah[p] = bh2; ax[p] = bx2;
            }

            // Recurrent part: 2 uniform lds128 per k deliver all 4 pairs.
#pragma unroll
            for (int k = 0; k < kH; k++) {
                u64 p0, p1, p2, p3;
                lds128(bufH + (uint32_t)k * 48,      p0, p1);
                lds128(bufH + (uint32_t)k * 48 + 16, p2, p3);
                u64 wz = pack2(Rz[k], Rz[k]);
                u64 wr = pack2(Rr[k], Rr[k]);
                float rh = sRh[k][lane];
                u64 wh = pack2(rh, rh);
                az[0] = fma2(p0, wz, az[0]); az[1] = fma2(p1, wz, az[1]);
                az[2] = fma2(p2, wz, az[2]); az[3] = fma2(p3, wz, az[3]);
                ar[0] = fma2(p0, wr, ar[0]); ar[1] = fma2(p1, wr, ar[1]);
                ar[2] = fma2(p2, wr, ar[2]); ar[3] = fma2(p3, wr, ar[3]);
                ah[0] = fma2(p0, wh, ah[0]); ah[1] = fma2(p1, wh, ah[1]);
                ah[2] = fma2(p2, wh, ah[2]); ah[3] = fma2(p3, wh, ah[3]);
            }
            // Feature part.
#pragma unroll
            for (int k = 0; k < kF; k++) {
                u64 p0, p1, p2, p3;
                lds128(bufX + (uint32_t)k * 48,      p0, p1);
                lds128(bufX + (uint32_t)k * 48 + 16, p2, p3);
                float w0 = sWin[0][k + 1][lane];
                float w1 = sWin[1][k + 1][lane];
                float w2 = sWin[2][k + 1][lane];
                u64 wz = pack2(w0, w0);
                u64 wr = pack2(w1, w1);
                u64 wx = pack2(w2, w2);
                az[0] = fma2(p0, wz, az[0]); az[1] = fma2(p1, wz, az[1]);
                az[2] = fma2(p2, wz, az[2]); az[3] = fma2(p3, wz, az[3]);
                ar[0] = fma2(p0, wr, ar[0]); ar[1] = fma2(p1, wr, ar[1]);
                ar[2] = fma2(p2, wr, ar[2]); ar[3] = fma2(p3, wr, ar[3]);
                ax[0] = fma2(p0, wx, ax[0]); ax[1] = fma2(p1, wx, ax[1]);
                ax[2] = fma2(p2, wx, ax[2]); ax[3] = fma2(p3, wx, ax[3]);
            }

            // Epilogue: prev-out terms (scalar, off the GEMM path) +
            // activations + state update, per batch.
#pragma unroll
            for (int p = 0; p < 4; p++) {
                float azl, azh, arl, arh, axl, axh, ahl, ahh;
                unpack2(az[p], azl, azh);
                unpack2(ar[p], arl, arh);
                unpack2(ax[p], axl, axh);
                unpack2(ah[p], ahl, ahh);
                {
                    int i = 2 * p;
                    float z = sig_fast(fmaf(Wz0, op[i], azl));
                    float r = sig_fast(fmaf(Wr0, op[i], arl));
                    float hh = tanh_fast(fmaf(r, ahl, fmaf(Wx0, op[i], axl)));
                    h[i] = fmaf(z, h[i] - hh, hh);
                }
                {
                    int i = 2 * p + 1;
                    float z = sig_fast(fmaf(Wz0, op[i], azh));
                    float r = sig_fast(fmaf(Wr0, op[i], arh));
                    float hh = tanh_fast(fmaf(r, ahh, fmaf(Wx0, op[i], axh)));
                    h[i] = fmaf(z, h[i] - hh, hh);
                }
            }
        }

        // Final outputs o_{T-1}.
#pragma unroll
        for (int i = 0; i < kBat; i++) {
            float o = redsum(h[i] * dwl) + dbv;
            if (lane == 0) ob[i * kT + (kT - 1)] = o;
        }
    }
}

extern "C" void kernel_launch(void* const* d_in, const int* in_sizes, int n_in,
                              void* d_out, int out_size) {
    (void)in_sizes; (void)n_in; (void)out_size;
    reset_counter_kernel<<<1, 1>>>();
    gru_decoder_kernel<<<kGrid, kCTA>>>(
        (const float*)d_in[0],   // decoder_feature
        (const float*)d_in[1],   // decoder_init_input
        (const float*)d_in[2],   // init_state
        (const float*)d_in[3],   // kernel
        (const float*)d_in[4],   // recurrent_kernel
        (const float*)d_in[5],   // bias_x
        (const float*)d_in[6],   // bias_h
        (const float*)d_in[7],   // dense_w
        (const float*)d_in[8],   // dense_b
        (float*)d_out);
}

// round 15
// speedup vs baseline: 1.4886x; 1.3419x over previous
#include <cuda_runtime.h>
#include <cuda_bf16.h>
#include <cstdint>

// GRU decoder (Keras reset_after=True), B=32768, T=48, F=16, H=32, fp32.
// Warp-level tensor cores (mma.sync.m16n8k16 bf16, baseline sm_80+ feature —
// the 'a'-features are unavailable with this build's family-generic PTX).
// One warp owns 32 batch rows (two m16 blocks). Per step, 320 mma compute
//   D[32 x 128] = A[32 x 160] @ B^T, N = [z(32) | r(32) | ax(32) | ah(32)]
// K layout (bf16 two-term splits; lo*lo dropped, ~2^-16):
//   kc0,1: h_hi (B:R_hi)  kc2,3: h_lo (B:R_hi)  kc4,5: h_hi (B:R_lo)
//   kc6: x_hi (B:W_hi)    kc7: x_lo (B:W_hi)    kc8: x_hi (B:W_lo)
//   kc9: k144,145,146 = p_hi,p_lo,p_hi (B: Wp_hi,Wp_hi,Wp_lo);
//        k147,148 = 1.0 (B: bias_hi, bias_lo); k149..159 = 0
// KEY: the m16n8 D-fragment layout == m16k16 A-fragment layout, so the new h
// produced by the epilogue becomes next step's A operand with pure in-thread
// cvt/pack — no shared round trips, no shuffles, no weight re-reads on fma.
// B is pre-arranged in shared in exact per-lane fragment order (LDS.64).

typedef unsigned long long u64;

namespace {
constexpr int kT    = 48;
constexpr int kCTA  = 64;     // 2 warps
constexpr int kGrid = 512;    // 512 CTAs x 64 batches = 32768
}

__device__ __forceinline__ uint32_t smem_u32(const void* p) {
    return (uint32_t)__cvta_generic_to_shared(p);
}
// pack two floats to bf16x2: first arg -> LOW half (lower k/col index)
__device__ __forceinline__ uint32_t packbf(float lo, float hi) {
    uint32_t d;
    asm("cvt.rn.bf16x2.f32 %0, %1, %2;" : "=r"(d) : "f"(hi), "f"(lo));
    return d;
}
__device__ __forceinline__ float2 unpk(uint32_t u) {
    __nv_bfloat162 v = *reinterpret_cast<__nv_bfloat162*>(&u);
    return make_float2(__low2float(v), __high2float(v));
}
__device__ __forceinline__ float fhi(float v) {
    return __bfloat162float(__float2bfloat16(v));
}
__device__ __forceinline__ void splitpack(float x, float y, uint32_t& hi, uint32_t& lo) {
    float h0 = fhi(x), h1 = fhi(y);
    hi = packbf(h0, h1);
    lo = packbf(x - h0, y - h1);
}
__device__ __forceinline__ float ex2a(float x) {
    float r; asm("ex2.approx.f32 %0, %1;" : "=f"(r) : "f"(x)); return r;
}
__device__ __forceinline__ float rcpa(float x) {
    float r; asm("rcp.approx.f32 %0, %1;" : "=f"(r) : "f"(x)); return r;
}
__device__ __forceinline__ float sig_fast(float x) {   // exact saturation at +/-inf
    return rcpa(1.0f + ex2a(-1.4426950408889634f * x));
}
__device__ __forceinline__ float tanh_fast(float x) {
    return fmaf(-2.0f, rcpa(1.0f + ex2a(2.8853900817779268f * x)), 1.0f);
}
__device__ __forceinline__ void lds64(uint32_t a, uint32_t& x, uint32_t& y) {
    asm volatile("ld.shared.v2.u32 {%0,%1}, [%2];" : "=r"(x), "=r"(y) : "r"(a));
}
__device__ __forceinline__ void mma16816(float d[4], const uint32_t a[4],
                                         uint32_t b0, uint32_t b1) {
    asm volatile(
        "mma.sync.aligned.m16n8k16.row.col.f32.bf16.bf16.f32 "
        "{%0,%1,%2,%3}, {%4,%5,%6,%7}, {%8,%9}, {%0,%1,%2,%3};"
        : "+f"(d[0]), "+f"(d[1]), "+f"(d[2]), "+f"(d[3])
        : "r"(a[0]), "r"(a[1]), "r"(a[2]), "r"(a[3]), "r"(b0), "r"(b1));
}

__global__ void __launch_bounds__(kCTA)
gru_mma_kernel(const float* __restrict__ feat,      // [B,T,F]
               const float* __restrict__ init_in,   // [B,1]
               const float* __restrict__ init_h,    // [B,H]
               const float* __restrict__ kern,      // [1+F, 3H]
               const float* __restrict__ rker,      // [H, 3H]
               const float* __restrict__ bx,        // [3H]
               const float* __restrict__ bh,        // [3H]
               const float* __restrict__ dw,        // [H,1]
               const float* __restrict__ db,        // [1]
               float* __restrict__ out)             // [B,T,1]
{
    // B fragments in exact mma order: [kc][nb][lane] -> {b0,b1} (8 bytes).
    // nb = gate*4 + g  (gate 0..3 = z,r,ax,ah; g = neuron-group, cols 8g..8g+7)
    __shared__ uint32_t Btab[10 * 16 * 32 * 2];   // 40 KB

    const int tid   = threadIdx.x;
    const int wip   = tid >> 5;
    const int lane  = tid & 31;
    const int c     = lane & 3;        // thread-in-quad
    const int rbase = lane >> 2;       // 0..7

    // ---- Build B table (once per CTA; weights are L1/L2-hot) ----
    for (int idx = tid; idx < 10 * 16 * 32; idx += kCTA) {
        int bl  = idx & 31;
        int nb  = (idx >> 5) & 15;
        int kc  = idx >> 9;
        int gate = nb >> 2, grp = nb & 3;
        int j = grp * 8 + (bl >> 2);          // neuron col within gate
        int bc = bl & 3;
        uint32_t regs[2];
#pragma unroll
        for (int hf = 0; hf < 2; hf++) {      // b0: k base, b1: k base+8
            float e[2];
#pragma unroll
            for (int e2 = 0; e2 < 2; e2++) {
                int kl = hf * 8 + bc * 2 + e2;   // 0..15 within chunk
                float w = 0.0f; int lo = 0;
                if (kc < 6) {                     // h sections
                    int sec = kc >> 1;            // 0 hi*Rhi, 1 lo*Rhi, 2 hi*Rlo
                    int hk = (kc & 1) * 16 + kl;  // 0..31
                    lo = (sec == 2);
                    if (gate == 0)      w = rker[hk * 96 + j];
                    else if (gate == 1) w = rker[hk * 96 + 32 + j];
                    else if (gate == 3) w = rker[hk * 96 + 64 + j];
                } else if (kc < 9) {              // x sections
                    lo = (kc == 8);
                    if (gate != 3) w = kern[(1 + kl) * 96 + gate * 32 + j];
                } else {                          // tail
                    if (kl <= 2) {                // prev_out weights
                        lo = (kl == 2);
                        if (gate != 3) w = kern[gate * 32 + j];
                    } else if (kl <= 4) {         // bias hi/lo
                        lo = (kl == 4);
                        w = (gate == 0) ? bx[j] + bh[j]
                          : (gate == 1) ? bx[32 + j] + bh[32 + j]
                          : (gate == 2) ? bx[64 + j] : bh[64 + j];
                    }
                }
                float whi = fhi(w);
                e[e2] = lo ? (w - whi) : whi;
            }
            regs[hf] = packbf(e[0], e[1]);
        }
        Btab[idx * 2]     = regs[0];
        Btab[idx * 2 + 1] = regs[1];
    }
    __syncthreads();
    const uint32_t btb = smem_u32(Btab);

    // ---- My 32 batch rows ----
    const int gb = blockIdx.x * 64 + wip * 32;
    // row(mb, rh) = gb + mb*16 + rbase + rh*8

    // Per-thread dense weights for my cols: dwv[g][e] = dw[8g + 2c + e]
    float dwv[4][2];
#pragma unroll
    for (int g = 0; g < 4; g++) {
        dwv[g][0] = dw[8 * g + 2 * c];
        dwv[g][1] = dw[8 * g + 2 * c + 1];
    }
    const float dbv = db[0];

    // ---- A fragments (bf16x2), register-resident ----
    uint32_t Ahi[2][2][4], Alo[2][2][4];   // h splits  [mb][chunk q][a0..a3]
    uint32_t Axh[2][4],   Axl[2][4];       // x splits  [mb][a0..a3]
    uint32_t Atl[2][4];                    // tail (prev + ones)

    // Init h fragments from init_h.
#pragma unroll
    for (int mb = 0; mb < 2; mb++) {
        int r0 = gb + mb * 16 + rbase;
#pragma unroll
        for (int q = 0; q < 2; q++) {
            float2 v00 = *reinterpret_cast<const float2*>(init_h + (size_t)r0 * 32 + q * 16 + 2 * c);
            float2 v10 = *reinterpret_cast<const float2*>(init_h + (size_t)(r0 + 8) * 32 + q * 16 + 2 * c);
            float2 v01 = *reinterpret_cast<const float2*>(init_h + (size_t)r0 * 32 + q * 16 + 8 + 2 * c);
            float2 v11 = *reinterpret_cast<const float2*>(init_h + (size_t)(r0 + 8) * 32 + q * 16 + 8 + 2 * c);
            splitpack(v00.x, v00.y, Ahi[mb][q][0], Alo[mb][q][0]);
            splitpack(v10.x, v10.y, Ahi[mb][q][1], Alo[mb][q][1]);
            splitpack(v01.x, v01.y, Ahi[mb][q][2], Alo[mb][q][2]);
            splitpack(v11.x, v11.y, Ahi[mb][q][3], Alo[mb][q][3]);
        }
    }
    // Init tail from init_in. Tail k-values per lane c:
    //  c0: (p_hi,p_lo)  c1: (p_hi,1)  c2: (1,0)  c3: (0,0); a2,a3 = 0
#pragma unroll
    for (int mb = 0; mb < 2; mb++) {
        int r0 = gb + mb * 16 + rbase;
#pragma unroll
        for (int rh = 0; rh < 2; rh++) {
            float p = init_in[r0 + rh * 8];
            float ph = fhi(p);
            uint32_t v = (c == 0) ? packbf(ph, p - ph)
                       : (c == 1) ? packbf(ph, 1.0f)
                       : (c == 2) ? packbf(1.0f, 0.0f) : 0u;
            Atl[mb][rh] = v;
        }
        Atl[mb][2] = 0u; Atl[mb][3] = 0u;
    }
    // Preload features for t=0.
    float2 xf2[2][2][2];   // [mb][rh][half]
#pragma unroll
    for (int mb = 0; mb < 2; mb++) {
#pragma unroll
        for (int rh = 0; rh < 2; rh++) {
            int row = gb + mb * 16 + rbase + rh * 8;
            const float* fr = feat + (size_t)row * (kT * 16);
            xf2[mb][rh][0] = *reinterpret_cast<const float2*>(fr + 2 * c);
            xf2[mb][rh][1] = *reinterpret_cast<const float2*>(fr + 8 + 2 * c);
        }
    }

#pragma unroll 1
    for (int t = 0; t < kT; t++) {
        // Build x fragments from prefetched values.
#pragma unroll
        for (int mb = 0; mb < 2; mb++) {
#pragma unroll
            for (int half = 0; half < 2; half++) {
#pragma unroll
                for (int rh = 0; rh < 2; rh++) {
                    float2 v = xf2[mb][rh][half];
                    splitpack(v.x, v.y, Axh[mb][half * 2 + rh], Axl[mb][half * 2 + rh]);
                }
            }
        }
        // Prefetch next step's features (consumed next iteration).
        if (t + 1 < kT) {
#pragma unroll
            for (int mb = 0; mb < 2; mb++) {
#pragma unroll
                for (int rh = 0; rh < 2; rh++) {
                    int row = gb + mb * 16 + rbase + rh * 8;
                    const float* fr = feat + (size_t)row * (kT * 16) + (t + 1) * 16;
                    xf2[mb][rh][0] = *reinterpret_cast<const float2*>(fr + 2 * c);
                    xf2[mb][rh][1] = *reinterpret_cast<const float2*>(fr + 8 + 2 * c);
                }
            }
        }

        uint32_t Nhi[2][2][4], Nlo[2][2][4];   // next-step h fragments
        float po[4] = {0.f, 0.f, 0.f, 0.f};    // dense partials per row

#pragma unroll
        for (int g = 0; g < 4; g++) {          // neuron-group: cols 8g..8g+7
            float D[4][2][4];
#pragma unroll
            for (int gt = 0; gt < 4; gt++)
#pragma unroll
                for (int mb = 0; mb < 2; mb++)
#pragma unroll
                    for (int e = 0; e < 4; e++) D[gt][mb][e] = 0.0f;

#pragma unroll
            for (int kc = 0; kc < 10; kc++) {
                uint32_t a0[4], a1[4];
#pragma unroll
                for (int e = 0; e < 4; e++) {
                    a0[e] = (kc == 0) ? Ahi[0][0][e] : (kc == 1) ? Ahi[0][1][e]
                          : (kc == 2) ? Alo[0][0][e] : (kc == 3) ? Alo[0][1][e]
                          : (kc == 4) ? Ahi[0][0][e] : (kc == 5) ? Ahi[0][1][e]
                          : (kc == 6) ? Axh[0][e]    : (kc == 7) ? Axl[0][e]
                          : (kc == 8) ? Axh[0][e]    : Atl[0][e];
                    a1[e] = (kc == 0) ? Ahi[1][0][e] : (kc == 1) ? Ahi[1][1][e]
                          : (kc == 2) ? Alo[1][0][e] : (kc == 3) ? Alo[1][1][e]
                          : (kc == 4) ? Ahi[1][0][e] : (kc == 5) ? Ahi[1][1][e]
                          : (kc == 6) ? Axh[1][e]    : (kc == 7) ? Axl[1][e]
                          : (kc == 8) ? Axh[1][e]    : Atl[1][e];
                }
#pragma unroll
                for (int gt = 0; gt < 4; gt++) {
                    int nb = gt * 4 + g;
                    uint32_t b0, b1;
                    lds64(btb + (uint32_t)(((kc * 16 + nb) * 32 + lane) * 8), b0, b1);
                    mma16816(D[gt][0], a0, b0, b1);
                    mma16816(D[gt][1], a1, b0, b1);
                }
            }

            // Epilogue for this group's 8 cols x 32 rows.
            const int q = g >> 1, pr = g & 1;
#pragma unroll
            for (int mb = 0; mb < 2; mb++) {
                float2 hi0 = unpk(Ahi[mb][q][2 * pr + 0]);
                float2 hi1 = unpk(Ahi[mb][q][2 * pr + 1]);
                float2 lo0 = unpk(Alo[mb][q][2 * pr + 0]);
                float2 lo1 = unpk(Alo[mb][q][2 * pr + 1]);
                float hold[4] = {hi0.x + lo0.x, hi0.y + lo0.y,
                                 hi1.x + lo1.x, hi1.y + lo1.y};
                float hn[4];
#pragma unroll
                for (int e = 0; e < 4; e++) {
                    float z = sig_fast(D[0][mb][e]);
                    float r = sig_fast(D[1][mb][e]);
                    float hh = tanh_fast(fmaf(r, D[3][mb][e], D[2][mb][e]));
                    hn[e] = fmaf(z, hold[e] - hh, hh);
                }
                po[mb * 2 + 0] = fmaf(dwv[g][0], hn[0], fmaf(dwv[g][1], hn[1], po[mb * 2 + 0]));
                po[mb * 2 + 1] = fmaf(dwv[g][0], hn[2], fmaf(dwv[g][1], hn[3], po[mb * 2 + 1]));
                splitpack(hn[0], hn[1], Nhi[mb][q][2 * pr + 0], Nlo[mb][q][2 * pr + 0]);
                splitpack(hn[2], hn[3], Nhi[mb][q][2 * pr + 1], Nlo[mb][q][2 * pr + 1]);
            }
        }

        // Commit new h fragments.
#pragma unroll
        for (int mb = 0; mb < 2; mb++)
#pragma unroll
            for (int q = 0; q < 2; q++)
#pragma unroll
                for (int e = 0; e < 4; e++) {
                    Ahi[mb][q][e] = Nhi[mb][q][e];
                    Alo[mb][q][e] = Nlo[mb][q][e];
                }

        // Dense(1): quad reduce (cols live on the 4 quad lanes).
#pragma unroll
        for (int i = 0; i < 4; i++) {
            po[i] += __shfl_xor_sync(0xffffffffu, po[i], 1);
            po[i] += __shfl_xor_sync(0xffffffffu, po[i], 2);
            po[i] += dbv;
        }
        // Write outputs + rebuild tail fragments for next step.
#pragma unroll
        for (int mb = 0; mb < 2; mb++) {
#pragma unroll
            for (int rh = 0; rh < 2; rh++) {
                float o = po[mb * 2 + rh];
                int row = gb + mb * 16 + rbase + rh * 8;
                if (c == 0) out[(size_t)row * kT + t] = o;
                float ph = fhi(o);
                uint32_t v = (c == 0) ? packbf(ph, o - ph)
                           : (c == 1) ? packbf(ph, 1.0f)
                           : (c == 2) ? packbf(1.0f, 0.0f) : 0u;
                Atl[mb][rh] = v;
            }
            Atl[mb][2] = 0u; Atl[mb][3] = 0u;
        }
    }
}

extern "C" void kernel_launch(void* const* d_in, const int* in_sizes, int n_in,
                              void* d_out, int out_size) {
    (void)in_sizes; (void)n_in; (void)out_size;
    gru_mma_kernel<<<kGrid, kCTA>>>(
        (const float*)d_in[0],   // decoder_feature
        (const float*)d_in[1],   // decoder_init_input
        (const float*)d_in[2],   // init_state
        (const float*)d_in[3],   // kernel
        (const float*)d_in[4],   // recurrent_kernel
        (const float*)d_in[5],   // bias_x
        (const float*)d_in[6],   // bias_h
        (const float*)d_in[7],   // dense_w
        (const float*)d_in[8],   // dense_b
        (float*)d_out);
}

// round 16
// speedup vs baseline: 1.9013x; 1.2772x over previous
#include <cuda_runtime.h>
#include <cuda_bf16.h>
#include <cstdint>

// GRU decoder (Keras reset_after=True), B=32768, T=48, F=16, H=32, fp32.
// Warp-level tensor cores (mma.sync.m16n8k16 bf16). One warp owns 16 batch
// rows. Per step:  D[16 x 128] = A[16 x 160] @ B^T, N = [z|r|ax|ah] (32 each).
// K layout (bf16 two-term splits; lo*lo dropped, ~2^-16):
//   kc0,1: h_hi (B:R_hi)  kc2,3: h_lo (B:R_hi)  kc4,5: h_hi (B:R_lo)
//   kc6: x_hi (B:W_hi)    kc7: x_lo (B:W_hi)    kc8: x_hi (B:W_lo)
//   kc9: k144..146 = p_hi,p_lo,p_hi (B: Wp_hi,Wp_hi,Wp_lo);
//        k147,148 = 1.0 (B: bias_hi, bias_lo); rest 0
// Zero-block pruning: z,r use kc0-9; ax uses kc6-9; ah uses kc0-5,9
// (124 MMAs/warp-step instead of 160).
// D-fragment layout == A-fragment layout: new h re-enters as next A in-regs.

typedef unsigned long long u64;

namespace {
constexpr int kT    = 48;
constexpr int kCTA  = 128;    // 4 warps x 16 rows = 64 batches per CTA
constexpr int kGrid = 512;    // 512 x 64 = 32768
}

__device__ __forceinline__ uint32_t smem_u32(const void* p) {
    return (uint32_t)__cvta_generic_to_shared(p);
}
// pack two floats to bf16x2: first arg -> LOW half
__device__ __forceinline__ uint32_t packbf(float lo, float hi) {
    uint32_t d;
    asm("cvt.rn.bf16x2.f32 %0, %1, %2;" : "=r"(d) : "f"(hi), "f"(lo));
    return d;
}
__device__ __forceinline__ float2 unpk(uint32_t u) {
    __nv_bfloat162 v = *reinterpret_cast<__nv_bfloat162*>(&u);
    return make_float2(__low2float(v), __high2float(v));
}
__device__ __forceinline__ float fhi(float v) {
    return __bfloat162float(__float2bfloat16(v));
}
__device__ __forceinline__ void splitpack(float x, float y, uint32_t& hi, uint32_t& lo) {
    float h0 = fhi(x), h1 = fhi(y);
    hi = packbf(h0, h1);
    lo = packbf(x - h0, y - h1);
}
__device__ __forceinline__ float ex2a(float x) {
    float r; asm("ex2.approx.f32 %0, %1;" : "=f"(r) : "f"(x)); return r;
}
__device__ __forceinline__ float rcpa(float x) {
    float r; asm("rcp.approx.f32 %0, %1;" : "=f"(r) : "f"(x)); return r;
}
__device__ __forceinline__ float sig_fast(float x) {
    return rcpa(1.0f + ex2a(-1.4426950408889634f * x));
}
__device__ __forceinline__ float tanh_fast(float x) {
    return fmaf(-2.0f, rcpa(1.0f + ex2a(2.8853900817779268f * x)), 1.0f);
}
__device__ __forceinline__ void lds64(uint32_t a, uint32_t& x, uint32_t& y) {
    asm volatile("ld.shared.v2.u32 {%0,%1}, [%2];" : "=r"(x), "=r"(y) : "r"(a));
}
__device__ __forceinline__ void mma16816(float d[4], const uint32_t a[4],
                                         uint32_t b0, uint32_t b1) {
    asm volatile(
        "mma.sync.aligned.m16n8k16.row.col.f32.bf16.bf16.f32 "
        "{%0,%1,%2,%3}, {%4,%5,%6,%7}, {%8,%9}, {%0,%1,%2,%3};"
        : "+f"(d[0]), "+f"(d[1]), "+f"(d[2]), "+f"(d[3])
        : "r"(a[0]), "r"(a[1]), "r"(a[2]), "r"(a[3]), "r"(b0), "r"(b1));
}

__global__ void __launch_bounds__(kCTA)
gru_mma_kernel(const float* __restrict__ feat,      // [B,T,F]
               const float* __restrict__ init_in,   // [B,1]
               const float* __restrict__ init_h,    // [B,H]
               const float* __restrict__ kern,      // [1+F, 3H]
               const float* __restrict__ rker,      // [H, 3H]
               const float* __restrict__ bx,        // [3H]
               const float* __restrict__ bh,        // [3H]
               const float* __restrict__ dw,        // [H,1]
               const float* __restrict__ db,        // [1]
               float* __restrict__ out)             // [B,T,1]
{
    // B fragments in exact mma order: [kc][nb][lane] -> {b0,b1} (8 bytes).
    // nb = gate*4 + grp  (gate 0..3 = z,r,ax,ah; grp -> cols 8*grp..8*grp+7)
    __shared__ uint32_t Btab[10 * 16 * 32 * 2];   // 40 KB

    const int tid   = threadIdx.x;
    const int wip   = tid >> 5;
    const int lane  = tid & 31;
    const int c     = lane & 3;        // thread-in-quad (col pair)
    const int rbase = lane >> 2;       // 0..7 (row within m16 half)

    // ---- Build B table (once per CTA) ----
    for (int idx = tid; idx < 10 * 16 * 32; idx += kCTA) {
        int bl  = idx & 31;
        int nb  = (idx >> 5) & 15;
        int kc  = idx >> 9;
        int gate = nb >> 2, grp = nb & 3;
        int j = grp * 8 + (bl >> 2);
        int bc = bl & 3;
        uint32_t regs[2];
#pragma unroll
        for (int hf = 0; hf < 2; hf++) {
            float e[2];
#pragma unroll
            for (int e2 = 0; e2 < 2; e2++) {
                int kl = hf * 8 + bc * 2 + e2;
                float w = 0.0f; int lo = 0;
                if (kc < 6) {                     // h sections
                    int sec = kc >> 1;            // 0 hi*Rhi, 1 lo*Rhi, 2 hi*Rlo
                    int hk = (kc & 1) * 16 + kl;
                    lo = (sec == 2);
                    if (gate == 0)      w = rker[hk * 96 + j];
                    else if (gate == 1) w = rker[hk * 96 + 32 + j];
                    else if (gate == 3) w = rker[hk * 96 + 64 + j];
                } else if (kc < 9) {              // x sections
                    lo = (kc == 8);
                    if (gate != 3) w = kern[(1 + kl) * 96 + gate * 32 + j];
                } else {                          // tail
                    if (kl <= 2) {
                        lo = (kl == 2);
                        if (gate != 3) w = kern[gate * 32 + j];
                    } else if (kl <= 4) {
                        lo = (kl == 4);
                        w = (gate == 0) ? bx[j] + bh[j]
                          : (gate == 1) ? bx[32 + j] + bh[32 + j]
                          : (gate == 2) ? bx[64 + j] : bh[64 + j];
                    }
                }
                float whi = fhi(w);
                e[e2] = lo ? (w - whi) : whi;
            }
            regs[hf] = packbf(e[0], e[1]);
        }
        Btab[idx * 2]     = regs[0];
        Btab[idx * 2 + 1] = regs[1];
    }
    __syncthreads();
    const uint32_t btb = smem_u32(Btab);

    // ---- My 16 batch rows: row(rh) = gb + rbase + rh*8 ----
    const int gb = (blockIdx.x * 4 + wip) * 16;

    float dwv[4][2];
#pragma unroll
    for (int g = 0; g < 4; g++) {
        dwv[g][0] = dw[8 * g + 2 * c];
        dwv[g][1] = dw[8 * g + 2 * c + 1];
    }
    const float dbv = db[0];

    // ---- A fragments (bf16x2), register-resident ----
    uint32_t Ahi[2][4], Alo[2][4];   // h splits [chunk q][a0..a3]
    uint32_t Axh[4], Axl[4];         // x splits
    uint32_t Atl[4];                 // tail (prev + ones)

#pragma unroll
    for (int q = 0; q < 2; q++) {
        int r0 = gb + rbase;
        float2 v00 = *reinterpret_cast<const float2*>(init_h + (size_t)r0 * 32 + q * 16 + 2 * c);
        float2 v10 = *reinterpret_cast<const float2*>(init_h + (size_t)(r0 + 8) * 32 + q * 16 + 2 * c);
        float2 v01 = *reinterpret_cast<const float2*>(init_h + (size_t)r0 * 32 + q * 16 + 8 + 2 * c);
        float2 v11 = *reinterpret_cast<const float2*>(init_h + (size_t)(r0 + 8) * 32 + q * 16 + 8 + 2 * c);
        splitpack(v00.x, v00.y, Ahi[q][0], Alo[q][0]);
        splitpack(v10.x, v10.y, Ahi[q][1], Alo[q][1]);
        splitpack(v01.x, v01.y, Ahi[q][2], Alo[q][2]);
        splitpack(v11.x, v11.y, Ahi[q][3], Alo[q][3]);
    }
    // Tail per lane c: c0 (p_hi,p_lo)  c1 (p_hi,1)  c2 (1,0)  c3 (0,0)
#pragma unroll
    for (int rh = 0; rh < 2; rh++) {
        float p = init_in[gb + rbase + rh * 8];
        float ph = fhi(p);
        Atl[rh] = (c == 0) ? packbf(ph, p - ph)
                : (c == 1) ? packbf(ph, 1.0f)
                : (c == 2) ? packbf(1.0f, 0.0f) : 0u;
    }
    Atl[2] = 0u; Atl[3] = 0u;

    float2 xf2[2][2];   // [rh][half] prefetched features
#pragma unroll
    for (int rh = 0; rh < 2; rh++) {
        const float* fr = feat + (size_t)(gb + rbase + rh * 8) * (kT * 16);
        xf2[rh][0] = *reinterpret_cast<const float2*>(fr + 2 * c);
        xf2[rh][1] = *reinterpret_cast<const float2*>(fr + 8 + 2 * c);
    }

#pragma unroll 1
    for (int t = 0; t < kT; t++) {
        // x fragments from prefetched values.
#pragma unroll
        for (int half = 0; half < 2; half++)
#pragma unroll
            for (int rh = 0; rh < 2; rh++) {
                float2 v = xf2[rh][half];
                splitpack(v.x, v.y, Axh[half * 2 + rh], Axl[half * 2 + rh]);
            }
        // Prefetch next step's features.
        if (t + 1 < kT) {
#pragma unroll
            for (int rh = 0; rh < 2; rh++) {
                const float* fr = feat + (size_t)(gb + rbase + rh * 8) * (kT * 16)
                                  + (t + 1) * 16;
                xf2[rh][0] = *reinterpret_cast<const float2*>(fr + 2 * c);
                xf2[rh][1] = *reinterpret_cast<const float2*>(fr + 8 + 2 * c);
            }
        }

        uint32_t Nhi[2][4], Nlo[2][4];
        float po[2] = {0.f, 0.f};

#pragma unroll
        for (int g = 0; g < 4; g++) {          // neuron-group: cols 8g..8g+7
            float D[4][4];
#pragma unroll
            for (int gt = 0; gt < 4; gt++)
#pragma unroll
                for (int e = 0; e < 4; e++) D[gt][e] = 0.0f;

#pragma unroll
            for (int kc = 0; kc < 10; kc++) {
                uint32_t a[4];
#pragma unroll
                for (int e = 0; e < 4; e++) {
                    a[e] = (kc == 0) ? Ahi[0][e] : (kc == 1) ? Ahi[1][e]
                         : (kc == 2) ? Alo[0][e] : (kc == 3) ? Alo[1][e]
                         : (kc == 4) ? Ahi[0][e] : (kc == 5) ? Ahi[1][e]
                         : (kc == 6) ? Axh[e]    : (kc == 7) ? Axl[e]
                         : (kc == 8) ? Axh[e]    : Atl[e];
                }
#pragma unroll
                for (int gt = 0; gt < 4; gt++) {
                    // prune structurally-zero B blocks:
                    // z,r: all kc; ax: kc>=6; ah: kc<6 or kc==9
                    if (gt == 2 && kc < 6) continue;
                    if (gt == 3 && (kc >= 6 && kc != 9)) continue;
                    int nb = gt * 4 + g;
                    uint32_t b0, b1;
                    lds64(btb + (uint32_t)(((kc * 16 + nb) * 32 + lane) * 8), b0, b1);
                    mma16816(D[gt], a, b0, b1);
                }
            }

            // Epilogue for this group's 8 cols x 16 rows.
            const int q = g >> 1, pr = g & 1;
            float2 hi0 = unpk(Ahi[q][2 * pr + 0]);
            float2 hi1 = unpk(Ahi[q][2 * pr + 1]);
            float2 lo0 = unpk(Alo[q][2 * pr + 0]);
            float2 lo1 = unpk(Alo[q][2 * pr + 1]);
            float hold[4] = {hi0.x + lo0.x, hi0.y + lo0.y,
                             hi1.x + lo1.x, hi1.y + lo1.y};
            float hn[4];
#pragma unroll
            for (int e = 0; e < 4; e++) {
                float z = sig_fast(D[0][e]);
                float r = sig_fast(D[1][e]);
                float hh = tanh_fast(fmaf(r, D[3][e], D[2][e]));
                hn[e] = fmaf(z, hold[e] - hh, hh);
            }
            po[0] = fmaf(dwv[g][0], hn[0], fmaf(dwv[g][1], hn[1], po[0]));
            po[1] = fmaf(dwv[g][0], hn[2], fmaf(dwv[g][1], hn[3], po[1]));
            splitpack(hn[0], hn[1], Nhi[q][2 * pr + 0], Nlo[q][2 * pr + 0]);
            splitpack(hn[2], hn[3], Nhi[q][2 * pr + 1], Nlo[q][2 * pr + 1]);
        }

        // Commit new h fragments.
#pragma unroll
        for (int q = 0; q < 2; q++)
#pragma unroll
            for (int e = 0; e < 4; e++) {
                Ahi[q][e] = Nhi[q][e];
                Alo[q][e] = Nlo[q][e];
            }

        // Dense(1): quad reduce; write + rebuild tail fragments.
#pragma unroll
        for (int rh = 0; rh < 2; rh++) {
            float o = po[rh];
            o += __shfl_xor_sync(0xffffffffu, o, 1);
            o += __shfl_xor_sync(0xffffffffu, o, 2);
            o += dbv;
            int row = gb + rbase + rh * 8;
            if (c == 0) out[(size_t)row * kT + t] = o;
            float ph = fhi(o);
            Atl[rh] = (c == 0) ? packbf(ph, o - ph)
                    : (c == 1) ? packbf(ph, 1.0f)
                    : (c == 2) ? packbf(1.0f, 0.0f) : 0u;
        }
    }
}

extern "C" void kernel_launch(void* const* d_in, const int* in_sizes, int n_in,
                              void* d_out, int out_size) {
    (void)in_sizes; (void)n_in; (void)out_size;
    gru_mma_kernel<<<kGrid, kCTA>>>(
        (const float*)d_in[0],   // decoder_feature
        (const float*)d_in[1],   // decoder_init_input
        (const float*)d_in[2],   // init_state
        (const float*)d_in[3],   // kernel
        (const float*)d_in[4],   // recurrent_kernel
        (const float*)d_in[5],   // bias_x
        (const float*)d_in[6],   // bias_h
        (const float*)d_in[7],   // dense_w
        (const float*)d_in[8],   // dense_b
        (float*)d_out);
}

// round 17
// speedup vs baseline: 1.9279x; 1.0140x over previous
#include <cuda_runtime.h>
#include <cuda_bf16.h>
#include <cstdint>

// GRU decoder (Keras reset_after=True), B=32768, T=48, F=16, H=32, fp32.
// Warp-level tensor cores (mma.sync.m16n8k16 bf16). One warp owns 16 batch
// rows. Per step:  D[16 x 128] = A[16 x 160] @ B^T, N = [z|r|ax|ah] (32 each).
// K layout (bf16 two-term splits; lo*lo dropped, ~2^-16):
//   kc0,1: h_hi (B:R_hi)  kc2,3: h_lo (B:R_hi)  kc4,5: h_hi (B:R_lo)
//   kc6: x_hi (B:W_hi)    kc7: x_lo (B:W_hi)    kc8: x_hi (B:W_lo)
//   kc9: k144..146 = p_hi,p_lo,p_hi (B: Wp_hi,Wp_hi,Wp_lo);
//        k147,148 = 1.0 (B: bias_hi, bias_lo); rest 0
// Zero-block pruning: z,r use kc0-9; ax uses kc6-9; ah uses kc0-5,9.
// R17 change: kc is the OUTER loop and all 16 (group, gate) D-accumulators
// stay live, giving ~12-16 independent MMA chains (vs 4) to cover the
// LDS->HMMA latency that pinned issue at ~52% in R16.

typedef unsigned long long u64;

namespace {
constexpr int kT    = 48;
constexpr int kCTA  = 128;    // 4 warps x 16 rows = 64 batches per CTA
constexpr int kGrid = 512;    // 512 x 64 = 32768
}

__device__ __forceinline__ uint32_t smem_u32(const void* p) {
    return (uint32_t)__cvta_generic_to_shared(p);
}
// pack two floats to bf16x2: first arg -> LOW half
__device__ __forceinline__ uint32_t packbf(float lo, float hi) {
    uint32_t d;
    asm("cvt.rn.bf16x2.f32 %0, %1, %2;" : "=r"(d) : "f"(hi), "f"(lo));
    return d;
}
__device__ __forceinline__ float2 unpk(uint32_t u) {
    __nv_bfloat162 v = *reinterpret_cast<__nv_bfloat162*>(&u);
    return make_float2(__low2float(v), __high2float(v));
}
__device__ __forceinline__ float fhi(float v) {
    return __bfloat162float(__float2bfloat16(v));
}
__device__ __forceinline__ void splitpack(float x, float y, uint32_t& hi, uint32_t& lo) {
    float h0 = fhi(x), h1 = fhi(y);
    hi = packbf(h0, h1);
    lo = packbf(x - h0, y - h1);
}
__device__ __forceinline__ float ex2a(float x) {
    float r; asm("ex2.approx.f32 %0, %1;" : "=f"(r) : "f"(x)); return r;
}
__device__ __forceinline__ float rcpa(float x) {
    float r; asm("rcp.approx.f32 %0, %1;" : "=f"(r) : "f"(x)); return r;
}
__device__ __forceinline__ float sig_fast(float x) {
    return rcpa(1.0f + ex2a(-1.4426950408889634f * x));
}
__device__ __forceinline__ float tanh_fast(float x) {
    return fmaf(-2.0f, rcpa(1.0f + ex2a(2.8853900817779268f * x)), 1.0f);
}
__device__ __forceinline__ void lds64(uint32_t a, uint32_t& x, uint32_t& y) {
    asm volatile("ld.shared.v2.u32 {%0,%1}, [%2];" : "=r"(x), "=r"(y) : "r"(a));
}
__device__ __forceinline__ void mma16816(float d[4], const uint32_t a[4],
                                         uint32_t b0, uint32_t b1) {
    asm volatile(
        "mma.sync.aligned.m16n8k16.row.col.f32.bf16.bf16.f32 "
        "{%0,%1,%2,%3}, {%4,%5,%6,%7}, {%8,%9}, {%0,%1,%2,%3};"
        : "+f"(d[0]), "+f"(d[1]), "+f"(d[2]), "+f"(d[3])
        : "r"(a[0]), "r"(a[1]), "r"(a[2]), "r"(a[3]), "r"(b0), "r"(b1));
}

__global__ void __launch_bounds__(kCTA, 3)
gru_mma_kernel(const float* __restrict__ feat,      // [B,T,F]
               const float* __restrict__ init_in,   // [B,1]
               const float* __restrict__ init_h,    // [B,H]
               const float* __restrict__ kern,      // [1+F, 3H]
               const float* __restrict__ rker,      // [H, 3H]
               const float* __restrict__ bx,        // [3H]
               const float* __restrict__ bh,        // [3H]
               const float* __restrict__ dw,        // [H,1]
               const float* __restrict__ db,        // [1]
               float* __restrict__ out)             // [B,T,1]
{
    // B fragments in exact mma order: [kc][nb][lane] -> {b0,b1} (8 bytes).
    // nb = gate*4 + grp  (gate 0..3 = z,r,ax,ah; grp -> cols 8*grp..8*grp+7)
    __shared__ uint32_t Btab[10 * 16 * 32 * 2];   // 40 KB

    const int tid   = threadIdx.x;
    const int wip   = tid >> 5;
    const int lane  = tid & 31;
    const int c     = lane & 3;        // thread-in-quad (col pair)
    const int rbase = lane >> 2;       // 0..7 (row within m16 half)

    // ---- Build B table (once per CTA) ----
    for (int idx = tid; idx < 10 * 16 * 32; idx += kCTA) {
        int bl  = idx & 31;
        int nb  = (idx >> 5) & 15;
        int kc  = idx >> 9;
        int gate = nb >> 2, grp = nb & 3;
        int j = grp * 8 + (bl >> 2);
        int bc = bl & 3;
        uint32_t regs[2];
#pragma unroll
        for (int hf = 0; hf < 2; hf++) {
            float e[2];
#pragma unroll
            for (int e2 = 0; e2 < 2; e2++) {
                int kl = hf * 8 + bc * 2 + e2;
                float w = 0.0f; int lo = 0;
                if (kc < 6) {                     // h sections
                    int sec = kc >> 1;            // 0 hi*Rhi, 1 lo*Rhi, 2 hi*Rlo
                    int hk = (kc & 1) * 16 + kl;
                    lo = (sec == 2);
                    if (gate == 0)      w = rker[hk * 96 + j];
                    else if (gate == 1) w = rker[hk * 96 + 32 + j];
                    else if (gate == 3) w = rker[hk * 96 + 64 + j];
                } else if (kc < 9) {              // x sections
                    lo = (kc == 8);
                    if (gate != 3) w = kern[(1 + kl) * 96 + gate * 32 + j];
                } else {                          // tail
                    if (kl <= 2) {
                        lo = (kl == 2);
                        if (gate != 3) w = kern[gate * 32 + j];
                    } else if (kl <= 4) {
                        lo = (kl == 4);
                        w = (gate == 0) ? bx[j] + bh[j]
                          : (gate == 1) ? bx[32 + j] + bh[32 + j]
                          : (gate == 2) ? bx[64 + j] : bh[64 + j];
                    }
                }
                float whi = fhi(w);
                e[e2] = lo ? (w - whi) : whi;
            }
            regs[hf] = packbf(e[0], e[1]);
        }
        Btab[idx * 2]     = regs[0];
        Btab[idx * 2 + 1] = regs[1];
    }
    __syncthreads();
    const uint32_t btb = smem_u32(Btab);

    // ---- My 16 batch rows: row(rh) = gb + rbase + rh*8 ----
    const int gb = (blockIdx.x * 4 + wip) * 16;

    float dwv[4][2];
#pragma unroll
    for (int g = 0; g < 4; g++) {
        dwv[g][0] = dw[8 * g + 2 * c];
        dwv[g][1] = dw[8 * g + 2 * c + 1];
    }
    const float dbv = db[0];

    // ---- A fragments (bf16x2), register-resident ----
    uint32_t Ahi[2][4], Alo[2][4];   // h splits [chunk q][a0..a3]
    uint32_t Axh[4], Axl[4];         // x splits
    uint32_t Atl[4];                 // tail (prev + ones)

#pragma unroll
    for (int q = 0; q < 2; q++) {
        int r0 = gb + rbase;
        float2 v00 = *reinterpret_cast<const float2*>(init_h + (size_t)r0 * 32 + q * 16 + 2 * c);
        float2 v10 = *reinterpret_cast<const float2*>(init_h + (size_t)(r0 + 8) * 32 + q * 16 + 2 * c);
        float2 v01 = *reinterpret_cast<const float2*>(init_h + (size_t)r0 * 32 + q * 16 + 8 + 2 * c);
        float2 v11 = *reinterpret_cast<const float2*>(init_h + (size_t)(r0 + 8) * 32 + q * 16 + 8 + 2 * c);
        splitpack(v00.x, v00.y, Ahi[q][0], Alo[q][0]);
        splitpack(v10.x, v10.y, Ahi[q][1], Alo[q][1]);
        splitpack(v01.x, v01.y, Ahi[q][2], Alo[q][2]);
        splitpack(v11.x, v11.y, Ahi[q][3], Alo[q][3]);
    }
    // Tail per lane c: c0 (p_hi,p_lo)  c1 (p_hi,1)  c2 (1,0)  c3 (0,0)
#pragma unroll
    for (int rh = 0; rh < 2; rh++) {
        float p = init_in[gb + rbase + rh * 8];
        float ph = fhi(p);
        Atl[rh] = (c == 0) ? packbf(ph, p - ph)
                : (c == 1) ? packbf(ph, 1.0f)
                : (c == 2) ? packbf(1.0f, 0.0f) : 0u;
    }
    Atl[2] = 0u; Atl[3] = 0u;

    float2 xf2[2][2];   // [rh][half] prefetched features
#pragma unroll
    for (int rh = 0; rh < 2; rh++) {
        const float* fr = feat + (size_t)(gb + rbase + rh * 8) * (kT * 16);
        xf2[rh][0] = *reinterpret_cast<const float2*>(fr + 2 * c);
        xf2[rh][1] = *reinterpret_cast<const float2*>(fr + 8 + 2 * c);
    }

#pragma unroll 1
    for (int t = 0; t < kT; t++) {
        // x fragments from prefetched values.
#pragma unroll
        for (int half = 0; half < 2; half++)
#pragma unroll
            for (int rh = 0; rh < 2; rh++) {
                float2 v = xf2[rh][half];
                splitpack(v.x, v.y, Axh[half * 2 + rh], Axl[half * 2 + rh]);
            }
        // Prefetch next step's features.
        if (t + 1 < kT) {
#pragma unroll
            for (int rh = 0; rh < 2; rh++) {
                const float* fr = feat + (size_t)(gb + rbase + rh * 8) * (kT * 16)
                                  + (t + 1) * 16;
                xf2[rh][0] = *reinterpret_cast<const float2*>(fr + 2 * c);
                xf2[rh][1] = *reinterpret_cast<const float2*>(fr + 8 + 2 * c);
            }
        }

        // ---- GEMM: kc outer, all 16 (g, gt) accumulators live (max ILP) ----
        float D[4][4][4];   // [g][gt][e]
#pragma unroll
        for (int g = 0; g < 4; g++)
#pragma unroll
            for (int gt = 0; gt < 4; gt++)
#pragma unroll
                for (int e = 0; e < 4; e++) D[g][gt][e] = 0.0f;

#pragma unroll
        for (int kc = 0; kc < 10; kc++) {
            uint32_t a[4];
#pragma unroll
            for (int e = 0; e < 4; e++) {
                a[e] = (kc == 0) ? Ahi[0][e] : (kc == 1) ? Ahi[1][e]
                     : (kc == 2) ? Alo[0][e] : (kc == 3) ? Alo[1][e]
                     : (kc == 4) ? Ahi[0][e] : (kc == 5) ? Ahi[1][e]
                     : (kc == 6) ? Axh[e]    : (kc == 7) ? Axl[e]
                     : (kc == 8) ? Axh[e]    : Atl[e];
            }
#pragma unroll
            for (int gt = 0; gt < 4; gt++) {
                // prune structurally-zero B blocks:
                // z,r: all kc; ax: kc>=6; ah: kc<6 or kc==9
                if (gt == 2 && kc < 6) continue;
                if (gt == 3 && (kc >= 6 && kc != 9)) continue;
#pragma unroll
                for (int g = 0; g < 4; g++) {
                    int nb = gt * 4 + g;
                    uint32_t b0, b1;
                    lds64(btb + (uint32_t)(((kc * 16 + nb) * 32 + lane) * 8), b0, b1);
                    mma16816(D[g][gt], a, b0, b1);
                }
            }
        }

        // ---- Epilogue per neuron-group ----
        uint32_t Nhi[2][4], Nlo[2][4];
        float po[2] = {0.f, 0.f};
#pragma unroll
        for (int g = 0; g < 4; g++) {
            const int q = g >> 1, pr = g & 1;
            float2 hi0 = unpk(Ahi[q][2 * pr + 0]);
            float2 hi1 = unpk(Ahi[q][2 * pr + 1]);
            float2 lo0 = unpk(Alo[q][2 * pr + 0]);
            float2 lo1 = unpk(Alo[q][2 * pr + 1]);
            float hold[4] = {hi0.x + lo0.x, hi0.y + lo0.y,
                             hi1.x + lo1.x, hi1.y + lo1.y};
            float hn[4];
#pragma unroll
            for (int e = 0; e < 4; e++) {
                float z = sig_fast(D[g][0][e]);
                float r = sig_fast(D[g][1][e]);
                float hh = tanh_fast(fmaf(r, D[g][3][e], D[g][2][e]));
                hn[e] = fmaf(z, hold[e] - hh, hh);
            }
            po[0] = fmaf(dwv[g][0], hn[0], fmaf(dwv[g][1], hn[1], po[0]));
            po[1] = fmaf(dwv[g][0], hn[2], fmaf(dwv[g][1], hn[3], po[1]));
            splitpack(hn[0], hn[1], Nhi[q][2 * pr + 0], Nlo[q][2 * pr + 0]);
            splitpack(hn[2], hn[3], Nhi[q][2 * pr + 1], Nlo[q][2 * pr + 1]);
        }

        // Commit new h fragments.
#pragma unroll
        for (int q = 0; q < 2; q++)
#pragma unroll
            for (int e = 0; e < 4; e++) {
                Ahi[q][e] = Nhi[q][e];
                Alo[q][e] = Nlo[q][e];
            }

        // Dense(1): quad reduce; write + rebuild tail fragments.
#pragma unroll
        for (int rh = 0; rh < 2; rh++) {
            float o = po[rh];
            o += __shfl_xor_sync(0xffffffffu, o, 1);
            o += __shfl_xor_sync(0xffffffffu, o, 2);
            o += dbv;
            int row = gb + rbase + rh * 8;
            if (c == 0) out[(size_t)row * kT + t] = o;
            float ph = fhi(o);
            Atl[rh] = (c == 0) ? packbf(ph, o - ph)
                    : (c == 1) ? packbf(ph, 1.0f)
                    : (c == 2) ? packbf(1.0f, 0.0f) : 0u;
        }
    }
}

extern "C" void kernel_launch(void* const* d_in, const int* in_sizes, int n_in,
                              void* d_out, int out_size) {
    (void)in_sizes; (void)n_in; (void)out_size;
    gru_mma_kernel<<<kGrid, kCTA>>>(
        (const float*)d_in[0],   // decoder_feature
        (const float*)d_in[1],   // decoder_init_input
        (const float*)d_in[2],   // init_state
        (const float*)d_in[3],   // kernel
        (const float*)d_in[4],   // recurrent_kernel
        (const float*)d_in[5],   // bias_x
        (const float*)d_in[6],   // bias_h
        (const float*)d_in[7],   // dense_w
        (const float*)d_in[8],   // dense_b
        (float*)d_out);
}